// round 15
// baseline (speedup 1.0000x reference)
#include <cuda_runtime.h>
#include <cuda_bf16.h>
#include <cstdint>

// Persistent LSTM: B=128, T=365, D=32, H=512, fp32 I/O, out[b,t,:]=h_t.
// R13 base: 128 CTAs x 256 threads (8 warps). CTA tile 32 batch(m) x 16
// units x 4 gates (n=64, n = u_local*4 + gate). Warp tile m16 x n16.
// GEMM: mma.sync m16n8k16 bf16, fp32 accum, 3-MMA hi/lo split.
// W resident in smem [n][k] bf16 hi/lo planes (pitch 1104B). A (h|x) in smem
// [k][hi32|lo32] rows (pitch 144B), staged via cp.async from g_h/g_x.
// R15: single producer counter (one poll+sync); h staged as 4x16KB commit
// groups with interleaved waits (finer pipeline); split accumulators
// (hh+lh chain / hl) to shorten dependent HMMA chains.

#define B_   128
#define T_   365
#define D_   32
#define H_   512
#define G4   2048
#define KTOT 544
#define NCTA 128
#define NTHR 256

#define SWP   1104                    // W row pitch bytes (552 bf16)
#define SWLO  (64 * SWP)              // lo-plane offset = 70656
#define SW_BYTES (128 * SWP)          // 141312
#define SAP   144                     // A row pitch bytes ([hi 64B | lo 64B] + pad)
#define SA_BYTES (KTOT * SAP)         // 78336
#define SMEM_BYTES (SW_BYTES + SA_BYTES)   // 219648

__device__ unsigned char g_h[2][4][512][128];   // [parity][mb][unit][hi32|lo32 bf16]
__device__ unsigned char g_x[4][T_][32][128];   // [mb][t][d][hi32|lo32 bf16]
__device__ unsigned int g_cnt[4];               // producers arrived (32/step)
__device__ unsigned int g_init[4];

__global__ void init_ctrl_kernel() {
    if (threadIdx.x < 4) { g_cnt[threadIdx.x] = 0u; g_init[threadIdx.x] = 0u; }
}

__device__ __forceinline__ float fsig(float z) {
    return 1.0f / (1.0f + __expf(-z));
}
__device__ __forceinline__ float ftanh_(float z) {
    return 1.0f - 2.0f / (__expf(2.0f * z) + 1.0f);
}
__device__ __forceinline__ void cp_async16(unsigned int smem_dst, const void* gsrc) {
    asm volatile("cp.async.cg.shared.global [%0], [%1], 16;"
                 :: "r"(smem_dst), "l"(gsrc) : "memory");
}
#define CP_COMMIT() asm volatile("cp.async.commit_group;" ::: "memory")
#define CP_WAIT(N)  asm volatile("cp.async.wait_group %0;" :: "n"(N) : "memory")
__device__ __forceinline__ unsigned int smem_u32(const void* p) {
    return (unsigned int)__cvta_generic_to_shared(p);
}
__device__ __forceinline__ unsigned int ld_acq(const unsigned int* p) {
    unsigned int v;
    asm volatile("ld.acquire.gpu.global.u32 %0, [%1];" : "=r"(v) : "l"(p));
    return v;
}
__device__ __forceinline__ void ldsm4(uint32_t& r0, uint32_t& r1, uint32_t& r2,
                                      uint32_t& r3, uint32_t a) {
    asm volatile("ldmatrix.sync.aligned.m8n8.x4.shared.b16 {%0,%1,%2,%3}, [%4];"
                 : "=r"(r0), "=r"(r1), "=r"(r2), "=r"(r3) : "r"(a));
}
__device__ __forceinline__ void ldsm4t(uint32_t& r0, uint32_t& r1, uint32_t& r2,
                                       uint32_t& r3, uint32_t a) {
    asm volatile("ldmatrix.sync.aligned.m8n8.x4.trans.shared.b16 {%0,%1,%2,%3}, [%4];"
                 : "=r"(r0), "=r"(r1), "=r"(r2), "=r"(r3) : "r"(a));
}
__device__ __forceinline__ void mma16816(float* c,
                                         uint32_t a0, uint32_t a1, uint32_t a2,
                                         uint32_t a3, uint32_t b0, uint32_t b1) {
    asm volatile(
        "mma.sync.aligned.m16n8k16.row.col.f32.bf16.bf16.f32 "
        "{%0,%1,%2,%3}, {%4,%5,%6,%7}, {%8,%9}, {%0,%1,%2,%3};"
        : "+f"(c[0]), "+f"(c[1]), "+f"(c[2]), "+f"(c[3])
        : "r"(a0), "r"(a1), "r"(a2), "r"(a3), "r"(b0), "r"(b1));
}
__device__ __forceinline__ void store_h_bf(unsigned char* row, int mloc, float h) {
    __nv_bfloat16 hi = __float2bfloat16(h);
    float lo = h - __bfloat162float(hi);
    *(__nv_bfloat16*)(row + mloc * 2) = hi;
    *(__nv_bfloat16*)(row + 64 + mloc * 2) = __float2bfloat16(lo);
}

// One k16 iteration: 4 ldmatrix + 6 mma. Split accumulators: accXa takes the
// hh+lh chain (depth 2), accXb takes hl (depth 1); merged in epilogue.
#define MMAIT(K0) do {                                                        \
    uint32_t ah0,ah1,ah2,ah3, al0,al1,al2,al3;                                \
    uint32_t bh0,bh1,bh2,bh3, bl0,bl1,bl2,bl3;                                \
    ldsm4t(ah0,ah1,ah2,ah3, aHi + (unsigned)(K0) * SAP);                      \
    ldsm4t(al0,al1,al2,al3, aHi + (unsigned)(K0) * SAP + 64u);                \
    ldsm4 (bh0,bh1,bh2,bh3, bHi + (unsigned)(K0) * 2u);                       \
    ldsm4 (bl0,bl1,bl2,bl3, bHi + (unsigned)(K0) * 2u + SWLO);                \
    mma16816(acc0a, ah0,ah1,ah2,ah3, bh0,bh1);                                \
    mma16816(acc1a, ah0,ah1,ah2,ah3, bh2,bh3);                                \
    mma16816(acc0b, ah0,ah1,ah2,ah3, bl0,bl1);                                \
    mma16816(acc1b, ah0,ah1,ah2,ah3, bl2,bl3);                                \
    mma16816(acc0a, al0,al1,al2,al3, bh0,bh1);                                \
    mma16816(acc1a, al0,al1,al2,al3, bh2,bh3);                                \
} while (0)

__global__ __launch_bounds__(NTHR, 1) void lstm_persistent(
    const float* __restrict__ x,    // [B,T,D]
    const float* __restrict__ Wx,   // [D,4H]
    const float* __restrict__ Wh,   // [H,4H]
    const float* __restrict__ bias, // [4H]
    float* __restrict__ out)        // [B,T,H]
{
    extern __shared__ char smem[];
    char* sA = smem + SW_BYTES;
    const unsigned int sWu = smem_u32(smem);
    const unsigned int sAu = smem_u32(sA);

    const int tid  = threadIdx.x;
    const int warp = tid >> 5;
    const int lane = tid & 31;
    const int mt   = warp & 1;               // m-tile (16 rows)
    const int nt   = warp >> 1;              // n-tile (16 gatecols = 4 units)
    const int ub   = blockIdx.x & 31;
    const int mb   = blockIdx.x >> 5;
    const int j0   = ub * 16;
    const int m0   = mb * 32;

    // ---- prologue: W -> bf16 hi/lo planes in smem, [n][k], n = u*4+g ----
    for (int i = 0; i < (64 * KTOT) / NTHR; ++i) {   // 136 iters
        int idx = i * NTHR + tid;
        int n = idx & 63;
        int k = idx >> 6;
        int col = (n & 3) * H_ + j0 + (n >> 2);
        float w = (k < H_) ? Wh[(size_t)k * G4 + col]
                           : Wx[(size_t)(k - H_) * G4 + col];
        __nv_bfloat16 hi = __float2bfloat16(w);
        float lo = w - __bfloat162float(hi);
        *(__nv_bfloat16*)(smem + n * SWP + k * 2) = hi;
        *(__nv_bfloat16*)(smem + SWLO + n * SWP + k * 2) = __float2bfloat16(lo);
    }

    // ---- prologue: transpose+convert this CTA's share of x into g_x ----
    {
        float* sX = (float*)sA;                      // scratch [32][33]
        for (int tt = ub; tt < T_; tt += 32) {
            float v[4];
            #pragma unroll
            for (int i = 0; i < 4; ++i) {
                int e = i * NTHR + tid;
                int m = e >> 5, d = e & 31;
                v[i] = x[(size_t)(m0 + m) * (T_ * D_) + (size_t)tt * D_ + d];
            }
            __syncthreads();
            #pragma unroll
            for (int i = 0; i < 4; ++i) {
                int e = i * NTHR + tid;
                int m = e >> 5, d = e & 31;
                sX[d * 33 + m] = v[i];
            }
            __syncthreads();
            unsigned char* gx = &g_x[mb][tt][0][0];
            #pragma unroll
            for (int i = 0; i < 4; ++i) {
                int e = i * NTHR + tid;
                int d = e >> 5, m = e & 31;
                float val = sX[d * 33 + m];
                __nv_bfloat16 hi = __float2bfloat16(val);
                float lo = val - __bfloat162float(hi);
                *(__nv_bfloat16*)(gx + d * 128 + m * 2) = hi;
                *(__nv_bfloat16*)(gx + d * 128 + 64 + m * 2) = __float2bfloat16(lo);
            }
            __syncthreads();
        }
    }

    // ---- zero A region; cross-CTA barrier for g_x; stage x(0) ----
    for (int i = tid; i < SA_BYTES / 4; i += NTHR) ((float*)sA)[i] = 0.f;
    __threadfence();
    __syncthreads();
    if (tid == 0) {
        atomicAdd(&g_init[mb], 1u);
        while (ld_acq(&g_init[mb]) < 32u) { }
    }
    __syncthreads();
    cp_async16(sAu + (unsigned)(512 + (tid >> 3)) * SAP + (tid & 7) * 16,
               &g_x[mb][0][0][0] + (tid >> 3) * 128 + (tid & 7) * 16);
    CP_COMMIT(); CP_WAIT(0);
    __syncthreads();

    // ---- per-lane fragment addresses ----
    const int li = lane & 7;
    const unsigned int aHi = sAu
        + (unsigned)((((lane >> 4) & 1) * 8 + li) * SAP)
        + (unsigned)((mt * 16 + ((lane >> 3) & 1) * 8) * 2);
    const unsigned int bHi = sWu
        + (unsigned)((nt * 16 + ((lane >> 4) & 1) * 8 + li) * SWP)
        + (unsigned)(((lane >> 3) & 1) * 16);

    // ---- per-lane epilogue constants (even lanes act) ----
    const int ul0 = nt * 4 + ((lane >> 1) & 1);
    const int jj0 = j0 + ul0;
    const int jj1 = jj0 + 2;
    const float bi0 = bias[jj0],      bf0 = bias[H_ + jj0];
    const float bg0 = bias[2*H_+jj0], bo0 = bias[3*H_+jj0];
    const float bi1 = bias[jj1],      bf1 = bias[H_ + jj1];
    const float bg1 = bias[2*H_+jj1], bo1 = bias[3*H_+jj1];
    float cS[4] = {0.f, 0.f, 0.f, 0.f};

    for (int t = 0; t < T_; ++t) {
        float acc0a[4] = {0.f,0.f,0.f,0.f}, acc0b[4] = {0.f,0.f,0.f,0.f};
        float acc1a[4] = {0.f,0.f,0.f,0.f}, acc1b[4] = {0.f,0.f,0.f,0.f};

        if (t > 0) {
            const unsigned char* hsrc = &g_h[(t - 1) & 1][mb][0][0];
            const unsigned char* xsrc = &g_x[mb][t][0][0];
            // group X: x(t), 4KB (x region of sAT free since prev step's start)
            cp_async16(sAu + (unsigned)(512 + (tid >> 3)) * SAP + (tid & 7) * 16,
                       xsrc + (tid >> 3) * 128 + (tid & 7) * 16);
            CP_COMMIT();
            // single poll: all 32 producers of this mb published h(t-1)
            if (tid == 0) {
                unsigned tgt = 32u * (unsigned)t;
                while (ld_acq(&g_cnt[mb]) < tgt) { }
            }
            __syncthreads();
            // h staged as 4 x 16KB commit groups (rows 128c..128c+127)
            #pragma unroll
            for (int c = 0; c < 4; ++c) {
                #pragma unroll
                for (int i = 0; i < 4; ++i) {
                    int g = c * 1024 + i * NTHR + tid;
                    int row = g >> 3, cc = g & 7;
                    cp_async16(sAu + (unsigned)row * SAP + cc * 16,
                               hsrc + row * 128 + cc * 16);
                }
                CP_COMMIT();
            }
            CP_WAIT(4);                       // X landed
            __syncthreads();
        }

        // x chunk first (h-independent; covers A1's flight)
        MMAIT(512); MMAIT(528);

        if (t > 0) { CP_WAIT(3); __syncthreads(); }
        #pragma unroll 2
        for (int k0 = 0; k0 < 128; k0 += 16) MMAIT(k0);

        if (t > 0) { CP_WAIT(2); __syncthreads(); }
        #pragma unroll 2
        for (int k0 = 128; k0 < 256; k0 += 16) MMAIT(k0);

        if (t > 0) { CP_WAIT(1); __syncthreads(); }
        #pragma unroll 2
        for (int k0 = 256; k0 < 384; k0 += 16) MMAIT(k0);

        if (t > 0) { CP_WAIT(0); __syncthreads(); }
        #pragma unroll 2
        for (int k0 = 384; k0 < 512; k0 += 16) MMAIT(k0);

        // merge split accumulators
        float acc0[4], acc1[4];
        #pragma unroll
        for (int i = 0; i < 4; ++i) {
            acc0[i] = acc0a[i] + acc0b[i];
            acc1[i] = acc1a[i] + acc1b[i];
        }

        // ---- epilogue: pair lanes (i,f)<->(g,o) via shfl.xor(1) ----
        float s0 = __shfl_xor_sync(0xffffffffu, acc0[0], 1);
        float s1 = __shfl_xor_sync(0xffffffffu, acc0[1], 1);
        float s2 = __shfl_xor_sync(0xffffffffu, acc0[2], 1);
        float s3 = __shfl_xor_sync(0xffffffffu, acc0[3], 1);
        float s4 = __shfl_xor_sync(0xffffffffu, acc1[0], 1);
        float s5 = __shfl_xor_sync(0xffffffffu, acc1[1], 1);
        float s6 = __shfl_xor_sync(0xffffffffu, acc1[2], 1);
        float s7 = __shfl_xor_sync(0xffffffffu, acc1[3], 1);

        if (!(lane & 1)) {
            const int r    = lane >> 2;
            const int mloc = mt * 16 + r;
            unsigned char* gh0 = &g_h[t & 1][mb][jj0][0];
            unsigned char* gh1 = &g_h[t & 1][mb][jj1][0];
            float* o0 = out + (size_t)(m0 + mloc) * ((size_t)T_ * H_) + (size_t)t * H_;
            float* o1 = out + (size_t)(m0 + mloc + 8) * ((size_t)T_ * H_) + (size_t)t * H_;
            {
                float ig = fsig(acc0[0] + bi0), fg = fsig(acc0[1] + bf0);
                float gg = ftanh_(s0 + bg0),    og = fsig(s1 + bo0);
                cS[0] = fg * cS[0] + ig * gg;
                float h = og * ftanh_(cS[0]);
                o0[jj0] = h; store_h_bf(gh0, mloc, h);
            }
            {
                float ig = fsig(acc0[2] + bi0), fg = fsig(acc0[3] + bf0);
                float gg = ftanh_(s2 + bg0),    og = fsig(s3 + bo0);
                cS[1] = fg * cS[1] + ig * gg;
                float h = og * ftanh_(cS[1]);
                o1[jj0] = h; store_h_bf(gh0, mloc + 8, h);
            }
            {
                float ig = fsig(acc1[0] + bi1), fg = fsig(acc1[1] + bf1);
                float gg = ftanh_(s4 + bg1),    og = fsig(s5 + bo1);
                cS[2] = fg * cS[2] + ig * gg;
                float h = og * ftanh_(cS[2]);
                o0[jj1] = h; store_h_bf(gh1, mloc, h);
            }
            {
                float ig = fsig(acc1[2] + bi1), fg = fsig(acc1[3] + bf1);
                float gg = ftanh_(s6 + bg1),    og = fsig(s7 + bo1);
                cS[3] = fg * cS[3] + ig * gg;
                float h = og * ftanh_(cS[3]);
                o1[jj1] = h; store_h_bf(gh1, mloc + 8, h);
            }
        }
        __syncthreads();
        if (tid == 0) {
            __threadfence();
            atomicAdd(&g_cnt[mb], 1u);
        }
    }
}

extern "C" void kernel_launch(void* const* d_in, const int* in_sizes, int n_in,
                              void* d_out, int out_size) {
    const float* x  = (const float*)d_in[0];
    const float* Wx = (const float*)d_in[1];
    const float* Wh = (const float*)d_in[2];
    const float* b  = (const float*)d_in[3];
    float* out = (float*)d_out;

    static bool attr_set = false;
    if (!attr_set) {
        cudaFuncSetAttribute(lstm_persistent,
                             cudaFuncAttributeMaxDynamicSharedMemorySize,
                             SMEM_BYTES);
        attr_set = true;
    }

    init_ctrl_kernel<<<1, 32>>>();
    lstm_persistent<<<NCTA, NTHR, SMEM_BYTES>>>(x, Wx, Wh, b, out);
}

// round 16
// speedup vs baseline: 1.5365x; 1.5365x over previous
#include <cuda_runtime.h>
#include <cuda_bf16.h>
#include <cstdint>

// Persistent LSTM: B=128, T=365, D=32, H=512, fp32 I/O, out[b,t,:]=h_t.
// R13 base (best: 2292us): 128 CTAs x 256 threads. CTA tile 32 batch(m) x
// 16 units x 4 gates (n=64, n = u_local*4 + gate). Warp tile m16 x n16.
// GEMM: mma.sync m16n8k16 bf16, fp32 accum, 3-MMA hi/lo split.
// W resident in smem [n][k] bf16 hi/lo planes (pitch 1104B). A (h|x) in smem
// [k][hi32|lo32] rows (pitch 144B), staged via cp.async groups X/A/B with
// x-chunk-first compute.
// R16 single delta: ONE producer counter g_cnt[mb] (was two halves) ->
// one tid-0 poll + one syncthreads per step instead of two of each.

#define B_   128
#define T_   365
#define D_   32
#define H_   512
#define G4   2048
#define KTOT 544
#define NCTA 128
#define NTHR 256

#define SWP   1104                    // W row pitch bytes (552 bf16)
#define SWLO  (64 * SWP)              // lo-plane offset = 70656
#define SW_BYTES (128 * SWP)          // 141312
#define SAP   144                     // A row pitch bytes ([hi 64B | lo 64B] + pad)
#define SA_BYTES (KTOT * SAP)         // 78336
#define SMEM_BYTES (SW_BYTES + SA_BYTES)   // 219648

__device__ unsigned char g_h[2][4][512][128];   // [parity][mb][unit][hi32|lo32 bf16]
__device__ unsigned char g_x[4][T_][32][128];   // [mb][t][d][hi32|lo32 bf16]
__device__ unsigned int g_cnt[4];               // producers arrived (32/step)
__device__ unsigned int g_init[4];

__global__ void init_ctrl_kernel() {
    if (threadIdx.x < 4) { g_cnt[threadIdx.x] = 0u; g_init[threadIdx.x] = 0u; }
}

__device__ __forceinline__ float fsig(float z) {
    return 1.0f / (1.0f + __expf(-z));
}
__device__ __forceinline__ float ftanh_(float z) {
    return 1.0f - 2.0f / (__expf(2.0f * z) + 1.0f);
}
__device__ __forceinline__ void cp_async16(unsigned int smem_dst, const void* gsrc) {
    asm volatile("cp.async.cg.shared.global [%0], [%1], 16;"
                 :: "r"(smem_dst), "l"(gsrc) : "memory");
}
#define CP_COMMIT() asm volatile("cp.async.commit_group;" ::: "memory")
#define CP_WAIT(N)  asm volatile("cp.async.wait_group %0;" :: "n"(N) : "memory")
__device__ __forceinline__ unsigned int smem_u32(const void* p) {
    return (unsigned int)__cvta_generic_to_shared(p);
}
__device__ __forceinline__ unsigned int ld_acq(const unsigned int* p) {
    unsigned int v;
    asm volatile("ld.acquire.gpu.global.u32 %0, [%1];" : "=r"(v) : "l"(p));
    return v;
}
__device__ __forceinline__ void ldsm4(uint32_t& r0, uint32_t& r1, uint32_t& r2,
                                      uint32_t& r3, uint32_t a) {
    asm volatile("ldmatrix.sync.aligned.m8n8.x4.shared.b16 {%0,%1,%2,%3}, [%4];"
                 : "=r"(r0), "=r"(r1), "=r"(r2), "=r"(r3) : "r"(a));
}
__device__ __forceinline__ void ldsm4t(uint32_t& r0, uint32_t& r1, uint32_t& r2,
                                       uint32_t& r3, uint32_t a) {
    asm volatile("ldmatrix.sync.aligned.m8n8.x4.trans.shared.b16 {%0,%1,%2,%3}, [%4];"
                 : "=r"(r0), "=r"(r1), "=r"(r2), "=r"(r3) : "r"(a));
}
__device__ __forceinline__ void mma16816(float* c,
                                         uint32_t a0, uint32_t a1, uint32_t a2,
                                         uint32_t a3, uint32_t b0, uint32_t b1) {
    asm volatile(
        "mma.sync.aligned.m16n8k16.row.col.f32.bf16.bf16.f32 "
        "{%0,%1,%2,%3}, {%4,%5,%6,%7}, {%8,%9}, {%0,%1,%2,%3};"
        : "+f"(c[0]), "+f"(c[1]), "+f"(c[2]), "+f"(c[3])
        : "r"(a0), "r"(a1), "r"(a2), "r"(a3), "r"(b0), "r"(b1));
}
__device__ __forceinline__ void store_h_bf(unsigned char* row, int mloc, float h) {
    __nv_bfloat16 hi = __float2bfloat16(h);
    float lo = h - __bfloat162float(hi);
    *(__nv_bfloat16*)(row + mloc * 2) = hi;
    *(__nv_bfloat16*)(row + 64 + mloc * 2) = __float2bfloat16(lo);
}

// One k16 iteration: 4 ldmatrix + 6 mma (hi*hi, hi*lo, lo*hi).
#define MMAIT(K0) do {                                                        \
    uint32_t ah0,ah1,ah2,ah3, al0,al1,al2,al3;                                \
    uint32_t bh0,bh1,bh2,bh3, bl0,bl1,bl2,bl3;                                \
    ldsm4t(ah0,ah1,ah2,ah3, aHi + (unsigned)(K0) * SAP);                      \
    ldsm4t(al0,al1,al2,al3, aHi + (unsigned)(K0) * SAP + 64u);                \
    ldsm4 (bh0,bh1,bh2,bh3, bHi + (unsigned)(K0) * 2u);                       \
    ldsm4 (bl0,bl1,bl2,bl3, bHi + (unsigned)(K0) * 2u + SWLO);                \
    mma16816(acc0, ah0,ah1,ah2,ah3, bh0,bh1);                                 \
    mma16816(acc1, ah0,ah1,ah2,ah3, bh2,bh3);                                 \
    mma16816(acc0, ah0,ah1,ah2,ah3, bl0,bl1);                                 \
    mma16816(acc1, ah0,ah1,ah2,ah3, bl2,bl3);                                 \
    mma16816(acc0, al0,al1,al2,al3, bh0,bh1);                                 \
    mma16816(acc1, al0,al1,al2,al3, bh2,bh3);                                 \
} while (0)

__global__ __launch_bounds__(NTHR, 1) void lstm_persistent(
    const float* __restrict__ x,    // [B,T,D]
    const float* __restrict__ Wx,   // [D,4H]
    const float* __restrict__ Wh,   // [H,4H]
    const float* __restrict__ bias, // [4H]
    float* __restrict__ out)        // [B,T,H]
{
    extern __shared__ char smem[];
    char* sA = smem + SW_BYTES;
    const unsigned int sWu = smem_u32(smem);
    const unsigned int sAu = smem_u32(sA);

    const int tid  = threadIdx.x;
    const int warp = tid >> 5;
    const int lane = tid & 31;
    const int mt   = warp & 1;               // m-tile (16 rows)
    const int nt   = warp >> 1;              // n-tile (16 gatecols = 4 units)
    const int ub   = blockIdx.x & 31;
    const int mb   = blockIdx.x >> 5;
    const int j0   = ub * 16;
    const int m0   = mb * 32;

    // ---- prologue: W -> bf16 hi/lo planes in smem, [n][k], n = u*4+g ----
    for (int i = 0; i < (64 * KTOT) / NTHR; ++i) {   // 136 iters
        int idx = i * NTHR + tid;
        int n = idx & 63;
        int k = idx >> 6;
        int col = (n & 3) * H_ + j0 + (n >> 2);
        float w = (k < H_) ? Wh[(size_t)k * G4 + col]
                           : Wx[(size_t)(k - H_) * G4 + col];
        __nv_bfloat16 hi = __float2bfloat16(w);
        float lo = w - __bfloat162float(hi);
        *(__nv_bfloat16*)(smem + n * SWP + k * 2) = hi;
        *(__nv_bfloat16*)(smem + SWLO + n * SWP + k * 2) = __float2bfloat16(lo);
    }

    // ---- prologue: transpose+convert this CTA's share of x into g_x ----
    {
        float* sX = (float*)sA;                      // scratch [32][33]
        for (int tt = ub; tt < T_; tt += 32) {
            float v[4];
            #pragma unroll
            for (int i = 0; i < 4; ++i) {
                int e = i * NTHR + tid;
                int m = e >> 5, d = e & 31;
                v[i] = x[(size_t)(m0 + m) * (T_ * D_) + (size_t)tt * D_ + d];
            }
            __syncthreads();
            #pragma unroll
            for (int i = 0; i < 4; ++i) {
                int e = i * NTHR + tid;
                int m = e >> 5, d = e & 31;
                sX[d * 33 + m] = v[i];
            }
            __syncthreads();
            unsigned char* gx = &g_x[mb][tt][0][0];
            #pragma unroll
            for (int i = 0; i < 4; ++i) {
                int e = i * NTHR + tid;
                int d = e >> 5, m = e & 31;
                float val = sX[d * 33 + m];
                __nv_bfloat16 hi = __float2bfloat16(val);
                float lo = val - __bfloat162float(hi);
                *(__nv_bfloat16*)(gx + d * 128 + m * 2) = hi;
                *(__nv_bfloat16*)(gx + d * 128 + 64 + m * 2) = __float2bfloat16(lo);
            }
            __syncthreads();
        }
    }

    // ---- zero A region; cross-CTA barrier for g_x; stage x(0) ----
    for (int i = tid; i < SA_BYTES / 4; i += NTHR) ((float*)sA)[i] = 0.f;
    __threadfence();
    __syncthreads();
    if (tid == 0) {
        atomicAdd(&g_init[mb], 1u);
        while (ld_acq(&g_init[mb]) < 32u) { }
    }
    __syncthreads();
    cp_async16(sAu + (unsigned)(512 + (tid >> 3)) * SAP + (tid & 7) * 16,
               &g_x[mb][0][0][0] + (tid >> 3) * 128 + (tid & 7) * 16);
    CP_COMMIT(); CP_WAIT(0);
    __syncthreads();

    // ---- per-lane fragment addresses ----
    const int li = lane & 7;
    const unsigned int aHi = sAu
        + (unsigned)((((lane >> 4) & 1) * 8 + li) * SAP)
        + (unsigned)((mt * 16 + ((lane >> 3) & 1) * 8) * 2);
    const unsigned int bHi = sWu
        + (unsigned)((nt * 16 + ((lane >> 4) & 1) * 8 + li) * SWP)
        + (unsigned)(((lane >> 3) & 1) * 16);

    // ---- per-lane epilogue constants (even lanes act) ----
    const int ul0 = nt * 4 + ((lane >> 1) & 1);
    const int jj0 = j0 + ul0;
    const int jj1 = jj0 + 2;
    const float bi0 = bias[jj0],      bf0 = bias[H_ + jj0];
    const float bg0 = bias[2*H_+jj0], bo0 = bias[3*H_+jj0];
    const float bi1 = bias[jj1],      bf1 = bias[H_ + jj1];
    const float bg1 = bias[2*H_+jj1], bo1 = bias[3*H_+jj1];
    float cS[4] = {0.f, 0.f, 0.f, 0.f};

    for (int t = 0; t < T_; ++t) {
        float acc0[4] = {0.f, 0.f, 0.f, 0.f};
        float acc1[4] = {0.f, 0.f, 0.f, 0.f};

        if (t > 0) {
            const unsigned char* hsrc = &g_h[(t - 1) & 1][mb][0][0];
            const unsigned char* xsrc = &g_x[mb][t][0][0];
            // group X: x(t), 4KB
            cp_async16(sAu + (unsigned)(512 + (tid >> 3)) * SAP + (tid & 7) * 16,
                       xsrc + (tid >> 3) * 128 + (tid & 7) * 16);
            CP_COMMIT();
            // SINGLE poll: all 32 producers of this mb published h(t-1)
            if (tid == 0) {
                unsigned tgt = 32u * (unsigned)t;
                while (ld_acq(&g_cnt[mb]) < tgt) { }
            }
            __syncthreads();
            // group A: h rows [0,256)
            #pragma unroll
            for (int i = 0; i < 8; ++i) {
                int g = i * NTHR + tid;
                int row = g >> 3, c = g & 7;
                cp_async16(sAu + (unsigned)row * SAP + c * 16,
                           hsrc + row * 128 + c * 16);
            }
            CP_COMMIT();
            // group B: h rows [256,512)
            #pragma unroll
            for (int i = 0; i < 8; ++i) {
                int g = 2048 + i * NTHR + tid;
                int row = g >> 3, c = g & 7;
                cp_async16(sAu + (unsigned)row * SAP + c * 16,
                           hsrc + row * 128 + c * 16);
            }
            CP_COMMIT();
            CP_WAIT(2);                      // X landed
            __syncthreads();
        }

        // x chunk first (h-independent; covers group A flight)
        MMAIT(512); MMAIT(528);

        if (t > 0) { CP_WAIT(1); __syncthreads(); }
        #pragma unroll 2
        for (int k0 = 0; k0 < 256; k0 += 16) MMAIT(k0);

        if (t > 0) { CP_WAIT(0); __syncthreads(); }
        #pragma unroll 2
        for (int k0 = 256; k0 < 512; k0 += 16) MMAIT(k0);

        // ---- epilogue: pair lanes (i,f)<->(g,o) via shfl.xor(1) ----
        float s0 = __shfl_xor_sync(0xffffffffu, acc0[0], 1);
        float s1 = __shfl_xor_sync(0xffffffffu, acc0[1], 1);
        float s2 = __shfl_xor_sync(0xffffffffu, acc0[2], 1);
        float s3 = __shfl_xor_sync(0xffffffffu, acc0[3], 1);
        float s4 = __shfl_xor_sync(0xffffffffu, acc1[0], 1);
        float s5 = __shfl_xor_sync(0xffffffffu, acc1[1], 1);
        float s6 = __shfl_xor_sync(0xffffffffu, acc1[2], 1);
        float s7 = __shfl_xor_sync(0xffffffffu, acc1[3], 1);

        if (!(lane & 1)) {
            const int r    = lane >> 2;           // 0..7
            const int mloc = mt * 16 + r;
            unsigned char* gh0 = &g_h[t & 1][mb][jj0][0];
            unsigned char* gh1 = &g_h[t & 1][mb][jj1][0];
            float* o0 = out + (size_t)(m0 + mloc) * ((size_t)T_ * H_) + (size_t)t * H_;
            float* o1 = out + (size_t)(m0 + mloc + 8) * ((size_t)T_ * H_) + (size_t)t * H_;

            {
                float ig = fsig(acc0[0] + bi0), fg = fsig(acc0[1] + bf0);
                float gg = ftanh_(s0 + bg0),    og = fsig(s1 + bo0);
                cS[0] = fg * cS[0] + ig * gg;
                float h = og * ftanh_(cS[0]);
                o0[jj0] = h; store_h_bf(gh0, mloc, h);
            }
            {
                float ig = fsig(acc0[2] + bi0), fg = fsig(acc0[3] + bf0);
                float gg = ftanh_(s2 + bg0),    og = fsig(s3 + bo0);
                cS[1] = fg * cS[1] + ig * gg;
                float h = og * ftanh_(cS[1]);
                o1[jj0] = h; store_h_bf(gh0, mloc + 8, h);
            }
            {
                float ig = fsig(acc1[0] + bi1), fg = fsig(acc1[1] + bf1);
                float gg = ftanh_(s4 + bg1),    og = fsig(s5 + bo1);
                cS[2] = fg * cS[2] + ig * gg;
                float h = og * ftanh_(cS[2]);
                o0[jj1] = h; store_h_bf(gh1, mloc, h);
            }
            {
                float ig = fsig(acc1[2] + bi1), fg = fsig(acc1[3] + bf1);
                float gg = ftanh_(s6 + bg1),    og = fsig(s7 + bo1);
                cS[3] = fg * cS[3] + ig * gg;
                float h = og * ftanh_(cS[3]);
                o1[jj1] = h; store_h_bf(gh1, mloc + 8, h);
            }
        }
        __syncthreads();
        if (tid == 0) {
            __threadfence();
            atomicAdd(&g_cnt[mb], 1u);
        }
    }
}

extern "C" void kernel_launch(void* const* d_in, const int* in_sizes, int n_in,
                              void* d_out, int out_size) {
    const float* x  = (const float*)d_in[0];
    const float* Wx = (const float*)d_in[1];
    const float* Wh = (const float*)d_in[2];
    const float* b  = (const float*)d_in[3];
    float* out = (float*)d_out;

    static bool attr_set = false;
    if (!attr_set) {
        cudaFuncSetAttribute(lstm_persistent,
                             cudaFuncAttributeMaxDynamicSharedMemorySize,
                             SMEM_BYTES);
        attr_set = true;
    }

    init_ctrl_kernel<<<1, 32>>>();
    lstm_persistent<<<NCTA, NTHR, SMEM_BYTES>>>(x, Wx, Wh, b, out);
}